// round 9
// baseline (speedup 1.0000x reference)
#include <cuda_runtime.h>
#include <cstdint>

// VectorQuantizer: F=32, N=4096, D=64, K=512
// out[f,n,:] = w[f,:,k*],  k* = argmin_k ||x - w_k||^2
// loss = 1.25 * mean((quantized - inputs)^2), appended at d_out[F*N*D]
//
// R9: 512 threads / 16 warps (4 per SMSP) for latency hiding. Warp pairs
//     split the k-space (8 k per lane -> acc2[8][4] = 64 regs), paired-d
//     x loads (LDS.128 gives dup x_d and x_{d+1}). Cross-warp argmin
//     combine via smem. Single kernel, deterministic loss.

#define Fh   32
#define Nh   4096
#define Dh   64
#define Kh   512
#define PADK 516                        // K + 4 floats: 16B-aligned rows
#define TILE_R 64
#define TILES_PER_F (Nh / TILE_R)       // 64
#define TOTAL_TILES (Fh * TILES_PER_F)  // 2048
#define THREADS 512

// smem: sw[64][516] f32 | swn[512] f32 | sx2[2][64*64] u64 | sxn[2][64] f32
#define SX2_OFF   (Dh * PADK + Kh)      // in floats (33536, 16B multiple)
#define SMEM_BYTES ((SX2_OFF + 2 * TILE_R * Dh * 2 + 2 * TILE_R) * 4)

__device__ double       g_part[256];
__device__ unsigned int g_count = 0;    // returns to 0 at end of every call

__device__ __forceinline__ unsigned long long ffma2(unsigned long long a,
                                                    unsigned long long b,
                                                    unsigned long long c) {
    unsigned long long d;
    asm("fma.rn.f32x2 %0, %1, %2, %3;" : "=l"(d) : "l"(a), "l"(b), "l"(c));
    return d;
}

__device__ __forceinline__ void unpack2(unsigned long long v, float& lo, float& hi) {
    unsigned int a, b;
    asm("mov.b64 {%0, %1}, %2;" : "=r"(a), "=r"(b) : "l"(v));
    lo = __uint_as_float(a);
    hi = __uint_as_float(b);
}

__global__ __launch_bounds__(THREADS, 1)
void vq_main_kernel(const float* __restrict__ x,
                    const float* __restrict__ w,
                    float* __restrict__ out,
                    int out_size) {
    extern __shared__ float smem[];
    float* sw  = smem;                                  // [Dh][PADK]
    float* swn = sw + Dh * PADK;                        // [Kh]
    unsigned long long* sx2 =
        (unsigned long long*)(smem + SX2_OFF);          // [2][TILE_R*Dh]: (-2x,-2x)
    float* sxn = (float*)(sx2 + 2 * TILE_R * Dh);       // [2][TILE_R] row ||x||^2

    __shared__ float  svals[16][8];
    __shared__ int    sidxs[16][8];
    __shared__ double warp_loss[16];
    __shared__ int    last_flag;

    const int tid   = threadIdx.x;
    const int wid   = tid >> 5;
    const int lane  = tid & 31;
    const int khalf = wid & 1;          // which 256-k half this warp covers
    const int grp   = wid >> 1;         // row group: rows grp*8 .. grp*8+7

    const int G   = gridDim.x;
    const int per = TOTAL_TILES / G;
    const int rem = TOTAL_TILES % G;
    const int t0  = blockIdx.x * per + (blockIdx.x < rem ? blockIdx.x : rem);
    const int cnt = per + (blockIdx.x < rem ? 1 : 0);
    const int tend = t0 + cnt;

    double lsum = 0.0;
    int cur_f = -1;
    int buf = 0;

    // Initial prefetch of tile t0's x (1024 float4, 2 per thread)
    float4 pf[2];
    {
        const int f0 = t0 >> 6, tl0 = t0 & 63;
        const float4* xg =
            (const float4*)(x + ((size_t)f0 * Nh + (size_t)tl0 * TILE_R) * Dh);
        #pragma unroll
        for (int j = 0; j < 2; ++j) pf[j] = xg[tid + THREADS * j];
    }

    for (int t = t0; t < tend; ++t) {
        const int f    = t >> 6;
        const int tile = t & 63;

        if (f != cur_f) {
            __syncthreads();  // prior readers of sw done
            const float4* wg = (const float4*)(w + (size_t)f * Dh * Kh);
            #pragma unroll 4
            for (int i = tid; i < Dh * (Kh / 4); i += THREADS) {
                const int d  = i >> 7;
                const int kq = i & 127;
                float4 v = wg[d * 128 + kq];
                *(float4*)&sw[d * PADK + kq * 4] = v;
            }
            __syncthreads();
            {   // one k per thread
                const int k = tid;
                float s = 0.f;
                #pragma unroll
                for (int d = 0; d < Dh; ++d) {
                    const float v = sw[d * PADK + k];
                    s = fmaf(v, v, s);
                }
                swn[k] = s;
            }
            cur_f = f;
            __syncthreads();
        }

        // ---- Store prefetched x as (-2x,-2x) pairs; row ||x||^2 ----
        {
            unsigned long long* dstb = sx2 + (size_t)buf * TILE_R * Dh;
            float s[2];
            #pragma unroll
            for (int j = 0; j < 2; ++j) {
                const int q   = tid + THREADS * j;
                const int row = q >> 4;
                const int dq  = q & 15;
                const float4 a = pf[j];
                unsigned long long* dst = dstb + row * Dh + dq * 4;
                const float nx = -2.f * a.x, ny = -2.f * a.y;
                const float nz = -2.f * a.z, nw = -2.f * a.w;
                *(float4*)(dst)     = make_float4(nx, nx, ny, ny);
                *(float4*)(dst + 2) = make_float4(nz, nz, nw, nw);
                float t2 = fmaf(a.x, a.x, a.y * a.y);
                t2 = fmaf(a.z, a.z, t2);
                s[j] = fmaf(a.w, a.w, t2);
            }
            // 16 consecutive lanes share a row
            #pragma unroll
            for (int off = 8; off > 0; off >>= 1)
                #pragma unroll
                for (int j = 0; j < 2; ++j)
                    s[j] += __shfl_xor_sync(0xffffffffu, s[j], off);
            if ((lane & 15) == 0) {
                #pragma unroll
                for (int j = 0; j < 2; ++j)
                    sxn[buf * TILE_R + ((tid + THREADS * j) >> 4)] = s[j];
            }
        }
        __syncthreads();   // barrier 1: x tile ready

        // ---- Mainloop: score_k = ||w_k||^2 + sum_d (-2 x_d) w_kd ----
        // This warp: 8 rows (grp*8..+7) x 8 k/lane (khalf's two 128-chunks).
        unsigned long long acc2[8][4];
        {
            const ulonglong2 n0 =
                *(const ulonglong2*)&swn[khalf * 256 + lane * 4];
            const ulonglong2 n1 =
                *(const ulonglong2*)&swn[khalf * 256 + 128 + lane * 4];
            #pragma unroll
            for (int r = 0; r < 8; ++r) {
                acc2[r][0] = n0.x; acc2[r][1] = n0.y;
                acc2[r][2] = n1.x; acc2[r][3] = n1.y;
            }
        }

        const float* swk = sw + khalf * 256 + lane * 4;
        const unsigned long long* xrow =
            sx2 + (size_t)buf * TILE_R * Dh + (grp * 8) * Dh;

        #pragma unroll 2
        for (int d = 0; d < Dh; d += 2) {
            const ulonglong2 w0a = *(const ulonglong2*)&swk[d * PADK];
            const ulonglong2 w0b = *(const ulonglong2*)&swk[d * PADK + 128];
            const ulonglong2 w1a = *(const ulonglong2*)&swk[(d + 1) * PADK];
            const ulonglong2 w1b = *(const ulonglong2*)&swk[(d + 1) * PADK + 128];
            const unsigned long long wp0[4] = {w0a.x, w0a.y, w0b.x, w0b.y};
            const unsigned long long wp1[4] = {w1a.x, w1a.y, w1b.x, w1b.y};
            #pragma unroll
            for (int h = 0; h < 2; ++h) {
                ulonglong2 xq[4];
                #pragma unroll
                for (int rr = 0; rr < 4; ++rr)
                    xq[rr] = *(const ulonglong2*)&xrow[(h * 4 + rr) * Dh + d];
                #pragma unroll
                for (int rr = 0; rr < 4; ++rr) {
                    const int r = h * 4 + rr;
                    #pragma unroll
                    for (int j = 0; j < 4; ++j) {
                        acc2[r][j] = ffma2(xq[rr].x, wp0[j], acc2[r][j]);
                        acc2[r][j] = ffma2(xq[rr].y, wp1[j], acc2[r][j]);
                    }
                }
            }
        }

        // ---- Per-lane argmin over this warp's 8 k (k ascending) ----
        float bval[8];
        int   bidx[8];
        #pragma unroll
        for (int r = 0; r < 8; ++r) { bval[r] = 3.4e38f; bidx[r] = 0; }

        #pragma unroll
        for (int c = 0; c < 2; ++c) {
            #pragma unroll
            for (int p = 0; p < 2; ++p) {
                const int klo = (khalf * 2 + c) * 128 + lane * 4 + p * 2;
                #pragma unroll
                for (int r = 0; r < 8; ++r) {
                    float slo, shi;
                    unpack2(acc2[r][c * 2 + p], slo, shi);
                    if (slo < bval[r]) { bval[r] = slo; bidx[r] = klo; }
                    if (shi < bval[r]) { bval[r] = shi; bidx[r] = klo + 1; }
                }
            }
        }

        // Prefetch next tile's x (overlaps reduce latency)
        if (t + 1 < tend) {
            const int f1 = (t + 1) >> 6, tl1 = (t + 1) & 63;
            const float4* xg =
                (const float4*)(x + ((size_t)f1 * Nh + (size_t)tl1 * TILE_R) * Dh);
            #pragma unroll
            for (int j = 0; j < 2; ++j) pf[j] = xg[tid + THREADS * j];
        }

        // Warp-level argmin reduce (tie -> smaller k)
        #pragma unroll
        for (int off = 16; off > 0; off >>= 1) {
            #pragma unroll
            for (int r = 0; r < 8; ++r) {
                const float ov = __shfl_down_sync(0xffffffffu, bval[r], off);
                const int   oi = __shfl_down_sync(0xffffffffu, bidx[r], off);
                if (ov < bval[r] || (ov == bval[r] && oi < bidx[r])) {
                    bval[r] = ov; bidx[r] = oi;
                }
            }
        }
        if (lane == 0) {
            #pragma unroll
            for (int r = 0; r < 8; ++r) {
                svals[wid][r] = bval[r];
                sidxs[wid][r] = bidx[r];
            }
        }
        __syncthreads();   // barrier 2: per-warp argmins visible

        // ---- Combine k-halves, gather codewords, accumulate loss ----
        // Warp handles rows wid*4 .. wid*4+3; all 4 rows lie in group `grp`,
        // local row index rr = khalf*4 + r'. Half-0 wins ties (smaller k).
        #pragma unroll
        for (int rp = 0; rp < 4; ++rp) {
            const int rr = khalf * 4 + rp;
            const float v0 = svals[grp * 2 + 0][rr];
            const float v1 = svals[grp * 2 + 1][rr];
            const int   k0 = sidxs[grp * 2 + 0][rr];
            const int   k1 = sidxs[grp * 2 + 1][rr];
            const int   kst = (v1 < v0) ? k1 : k0;
            const int   row = wid * 4 + rp;     // == grp*8 + rr
            if (lane == 0) {
                const float vm = (v1 < v0) ? v1 : v0;
                lsum += (double)(vm + sxn[buf * TILE_R + row]);
            }
            const int n = tile * TILE_R + row;
            float* orow = out + ((size_t)f * Nh + n) * Dh;
            #pragma unroll
            for (int it = 0; it < 2; ++it) {
                const int d = it * 32 + lane;
                orow[d] = sw[d * PADK + kst];
            }
        }
        buf ^= 1;
    }

    // ---- Block partial -> last-block deterministic reduction ----
    if (lane == 0) warp_loss[wid] = lsum;
    __syncthreads();
    if (tid == 0) {
        double bl = 0.0;
        #pragma unroll
        for (int i = 0; i < 16; ++i) bl += warp_loss[i];
        g_part[blockIdx.x] = bl;
        __threadfence();
        const unsigned c = atomicAdd(&g_count, 1u);
        last_flag = (c == (unsigned)(G - 1)) ? 1 : 0;
    }
    __syncthreads();
    if (last_flag && wid == 0) {
        double s = 0.0;
        for (int i = lane; i < G; i += 32) s += g_part[i];
        #pragma unroll
        for (int off = 16; off > 0; off >>= 1)
            s += __shfl_down_sync(0xffffffffu, s, off);
        if (lane == 0) {
            const long long nelem = (long long)Fh * Nh * Dh;
            if (out_size > (int)nelem)
                out[nelem] = (float)(1.25 * s / (double)nelem);
            g_count = 0;   // reset for next call
        }
    }
}

extern "C" void kernel_launch(void* const* d_in, const int* in_sizes, int n_in,
                              void* d_out, int out_size) {
    const float* x = (const float*)d_in[0];
    const float* w = (const float*)d_in[1];
    if (n_in >= 2 && in_sizes[0] == Fh * Dh * Kh && in_sizes[1] == Fh * Nh * Dh) {
        const float* tmp = x; x = w; w = tmp;
    }
    float* out = (float*)d_out;

    cudaFuncSetAttribute(vq_main_kernel,
                         cudaFuncAttributeMaxDynamicSharedMemorySize, SMEM_BYTES);

    int sms = 148;
    cudaDeviceGetAttribute(&sms, cudaDevAttrMultiProcessorCount, 0);
    if (sms <= 0) sms = 148;
    if (sms > 256) sms = 256;           // g_part capacity
    if (sms > TOTAL_TILES) sms = TOTAL_TILES;

    vq_main_kernel<<<sms, THREADS, SMEM_BYTES>>>(x, w, out, out_size);
}

// round 10
// speedup vs baseline: 1.1354x; 1.1354x over previous
#include <cuda_runtime.h>
#include <cstdint>

// VectorQuantizer: F=32, N=4096, D=64, K=512
// out[f,n,:] = w[f,:,k*],  k* = argmin_k ||x - w_k||^2
// loss = 1.25 * mean((quantized - inputs)^2), appended at d_out[F*N*D]
//
// R10: tiling r=4 rows/warp x kl=16 k/lane, 512 threads (16 warps, 4/SMSP).
//      Crossbar 192 cyc/d/SM < FMA 256 cyc/d/SM -> FMA-bound, and
//      acc2[4][8]=64 regs -> ~115 regs/thread, real scheduling headroom.
//      Each warp covers full k for its rows: no cross-warp combine,
//      one barrier per tile. Deterministic single-kernel loss.

#define Fh   32
#define Nh   4096
#define Dh   64
#define Kh   512
#define PADK 516                        // K + 4 floats: 16B-aligned rows
#define TILE_R 64
#define TILES_PER_F (Nh / TILE_R)       // 64
#define TOTAL_TILES (Fh * TILES_PER_F)  // 2048
#define THREADS 512

// smem: sw[64][516] f32 | swn[512] f32 | sx2[2][64*64] u64 | sxn[2][64] f32
#define SX2_OFF   (Dh * PADK + Kh)      // in floats (33536, 16B multiple)
#define SMEM_BYTES ((SX2_OFF + 2 * TILE_R * Dh * 2 + 2 * TILE_R) * 4)

__device__ double       g_part[256];
__device__ unsigned int g_count = 0;    // returns to 0 at end of every call

__device__ __forceinline__ unsigned long long ffma2(unsigned long long a,
                                                    unsigned long long b,
                                                    unsigned long long c) {
    unsigned long long d;
    asm("fma.rn.f32x2 %0, %1, %2, %3;" : "=l"(d) : "l"(a), "l"(b), "l"(c));
    return d;
}

__device__ __forceinline__ void unpack2(unsigned long long v, float& lo, float& hi) {
    unsigned int a, b;
    asm("mov.b64 {%0, %1}, %2;" : "=r"(a), "=r"(b) : "l"(v));
    lo = __uint_as_float(a);
    hi = __uint_as_float(b);
}

__global__ __launch_bounds__(THREADS, 1)
void vq_main_kernel(const float* __restrict__ x,
                    const float* __restrict__ w,
                    float* __restrict__ out,
                    int out_size) {
    extern __shared__ float smem[];
    float* sw  = smem;                                  // [Dh][PADK]
    float* swn = sw + Dh * PADK;                        // [Kh]
    unsigned long long* sx2 =
        (unsigned long long*)(smem + SX2_OFF);          // [2][TILE_R*Dh]: (-2x,-2x)
    float* sxn = (float*)(sx2 + 2 * TILE_R * Dh);       // [2][TILE_R] row ||x||^2

    __shared__ double warp_loss[16];
    __shared__ int    last_flag;

    const int tid  = threadIdx.x;
    const int wid  = tid >> 5;          // warp owns rows wid*4 .. wid*4+3
    const int lane = tid & 31;

    const int G   = gridDim.x;
    const int per = TOTAL_TILES / G;
    const int rem = TOTAL_TILES % G;
    const int t0  = blockIdx.x * per + (blockIdx.x < rem ? blockIdx.x : rem);
    const int cnt = per + (blockIdx.x < rem ? 1 : 0);
    const int tend = t0 + cnt;

    double lsum = 0.0;
    int cur_f = -1;
    int buf = 0;

    // Initial prefetch of tile t0's x (1024 float4, 2 per thread)
    float4 pf[2];
    {
        const int f0 = t0 >> 6, tl0 = t0 & 63;
        const float4* xg =
            (const float4*)(x + ((size_t)f0 * Nh + (size_t)tl0 * TILE_R) * Dh);
        #pragma unroll
        for (int j = 0; j < 2; ++j) pf[j] = xg[tid + THREADS * j];
    }

    for (int t = t0; t < tend; ++t) {
        const int f    = t >> 6;
        const int tile = t & 63;

        if (f != cur_f) {
            __syncthreads();  // prior readers of sw done
            const float4* wg = (const float4*)(w + (size_t)f * Dh * Kh);
            #pragma unroll 4
            for (int i = tid; i < Dh * (Kh / 4); i += THREADS) {
                const int d  = i >> 7;
                const int kq = i & 127;
                float4 v = wg[d * 128 + kq];
                *(float4*)&sw[d * PADK + kq * 4] = v;
            }
            __syncthreads();
            {   // one k per thread
                const int k = tid;
                float s = 0.f;
                #pragma unroll
                for (int d = 0; d < Dh; ++d) {
                    const float v = sw[d * PADK + k];
                    s = fmaf(v, v, s);
                }
                swn[k] = s;
            }
            cur_f = f;
            __syncthreads();
        }

        // ---- Store prefetched x as (-2x,-2x) pairs; row ||x||^2 ----
        {
            unsigned long long* dstb = sx2 + (size_t)buf * TILE_R * Dh;
            float s[2];
            #pragma unroll
            for (int j = 0; j < 2; ++j) {
                const int q   = tid + THREADS * j;
                const int row = q >> 4;
                const int dq  = q & 15;
                const float4 a = pf[j];
                unsigned long long* dst = dstb + row * Dh + dq * 4;
                const float nx = -2.f * a.x, ny = -2.f * a.y;
                const float nz = -2.f * a.z, nw = -2.f * a.w;
                *(float4*)(dst)     = make_float4(nx, nx, ny, ny);
                *(float4*)(dst + 2) = make_float4(nz, nz, nw, nw);
                float t2 = fmaf(a.x, a.x, a.y * a.y);
                t2 = fmaf(a.z, a.z, t2);
                s[j] = fmaf(a.w, a.w, t2);
            }
            // 16 consecutive lanes share a row
            #pragma unroll
            for (int off = 8; off > 0; off >>= 1)
                #pragma unroll
                for (int j = 0; j < 2; ++j)
                    s[j] += __shfl_xor_sync(0xffffffffu, s[j], off);
            if ((lane & 15) == 0) {
                #pragma unroll
                for (int j = 0; j < 2; ++j)
                    sxn[buf * TILE_R + ((tid + THREADS * j) >> 4)] = s[j];
            }
        }
        __syncthreads();   // single barrier per tile

        // ---- Mainloop: score_k = ||w_k||^2 + sum_d (-2 x_d) w_kd ----
        // Warp: 4 rows (wid*4..+3) x 16 k/lane (k = c*128 + lane*4 + j).
        unsigned long long acc2[4][8];
        {
            #pragma unroll
            for (int c = 0; c < 4; ++c) {
                const ulonglong2 nv =
                    *(const ulonglong2*)&swn[c * 128 + lane * 4];
                #pragma unroll
                for (int r = 0; r < 4; ++r) {
                    acc2[r][2 * c + 0] = nv.x;
                    acc2[r][2 * c + 1] = nv.y;
                }
            }
        }

        const float* swk = sw + lane * 4;
        const unsigned long long* xrow =
            sx2 + (size_t)buf * TILE_R * Dh + (wid * 4) * Dh;

        #pragma unroll 4
        for (int d = 0; d < Dh; ++d) {
            unsigned long long wp[8];
            #pragma unroll
            for (int c = 0; c < 4; ++c) {
                const ulonglong2 v =
                    *(const ulonglong2*)&swk[d * PADK + c * 128];
                wp[2 * c + 0] = v.x;
                wp[2 * c + 1] = v.y;
            }
            unsigned long long xp[4];
            #pragma unroll
            for (int r = 0; r < 4; ++r) xp[r] = xrow[r * Dh + d];  // broadcast
            #pragma unroll
            for (int r = 0; r < 4; ++r)
                #pragma unroll
                for (int j = 0; j < 8; ++j)
                    acc2[r][j] = ffma2(xp[r], wp[j], acc2[r][j]);
        }

        // ---- Per-lane argmin over 16 k (k ascending within lane) ----
        float bval[4];
        int   bidx[4];
        #pragma unroll
        for (int r = 0; r < 4; ++r) { bval[r] = 3.4e38f; bidx[r] = 0; }

        #pragma unroll
        for (int c = 0; c < 4; ++c) {
            #pragma unroll
            for (int p = 0; p < 2; ++p) {
                const int klo = c * 128 + lane * 4 + p * 2;
                #pragma unroll
                for (int r = 0; r < 4; ++r) {
                    float slo, shi;
                    unpack2(acc2[r][c * 2 + p], slo, shi);
                    if (slo < bval[r]) { bval[r] = slo; bidx[r] = klo; }
                    if (shi < bval[r]) { bval[r] = shi; bidx[r] = klo + 1; }
                }
            }
        }

        // Prefetch next tile's x (overlaps reduce latency)
        if (t + 1 < tend) {
            const int f1 = (t + 1) >> 6, tl1 = (t + 1) & 63;
            const float4* xg =
                (const float4*)(x + ((size_t)f1 * Nh + (size_t)tl1 * TILE_R) * Dh);
            #pragma unroll
            for (int j = 0; j < 2; ++j) pf[j] = xg[tid + THREADS * j];
        }

        // Warp-level argmin reduce (tie -> smaller k)
        #pragma unroll
        for (int off = 16; off > 0; off >>= 1) {
            #pragma unroll
            for (int r = 0; r < 4; ++r) {
                const float ov = __shfl_down_sync(0xffffffffu, bval[r], off);
                const int   oi = __shfl_down_sync(0xffffffffu, bidx[r], off);
                if (ov < bval[r] || (ov == bval[r] && oi < bidx[r])) {
                    bval[r] = ov; bidx[r] = oi;
                }
            }
        }
        // Loss: dist = ||x||^2 + min score
        if (lane == 0) {
            #pragma unroll
            for (int r = 0; r < 4; ++r)
                lsum += (double)(bval[r] + sxn[buf * TILE_R + wid * 4 + r]);
        }
        #pragma unroll
        for (int r = 0; r < 4; ++r)
            bidx[r] = __shfl_sync(0xffffffffu, bidx[r], 0);

        // ---- Gather winning codewords, write output ----
        #pragma unroll
        for (int r = 0; r < 4; ++r) {
            const int kst = bidx[r];
            const int n = tile * TILE_R + wid * 4 + r;
            float* orow = out + ((size_t)f * Nh + n) * Dh;
            #pragma unroll
            for (int it = 0; it < 2; ++it) {
                const int d = it * 32 + lane;
                orow[d] = sw[d * PADK + kst];
            }
        }
        buf ^= 1;
    }

    // ---- Block partial -> last-block deterministic reduction ----
    if (lane == 0) warp_loss[wid] = lsum;
    __syncthreads();
    if (tid == 0) {
        double bl = 0.0;
        #pragma unroll
        for (int i = 0; i < 16; ++i) bl += warp_loss[i];
        g_part[blockIdx.x] = bl;
        __threadfence();
        const unsigned c = atomicAdd(&g_count, 1u);
        last_flag = (c == (unsigned)(G - 1)) ? 1 : 0;
    }
    __syncthreads();
    if (last_flag && wid == 0) {
        double s = 0.0;
        for (int i = lane; i < G; i += 32) s += g_part[i];
        #pragma unroll
        for (int off = 16; off > 0; off >>= 1)
            s += __shfl_down_sync(0xffffffffu, s, off);
        if (lane == 0) {
            const long long nelem = (long long)Fh * Nh * Dh;
            if (out_size > (int)nelem)
                out[nelem] = (float)(1.25 * s / (double)nelem);
            g_count = 0;   // reset for next call
        }
    }
}

extern "C" void kernel_launch(void* const* d_in, const int* in_sizes, int n_in,
                              void* d_out, int out_size) {
    const float* x = (const float*)d_in[0];
    const float* w = (const float*)d_in[1];
    if (n_in >= 2 && in_sizes[0] == Fh * Dh * Kh && in_sizes[1] == Fh * Nh * Dh) {
        const float* tmp = x; x = w; w = tmp;
    }
    float* out = (float*)d_out;

    cudaFuncSetAttribute(vq_main_kernel,
                         cudaFuncAttributeMaxDynamicSharedMemorySize, SMEM_BYTES);

    int sms = 148;
    cudaDeviceGetAttribute(&sms, cudaDevAttrMultiProcessorCount, 0);
    if (sms <= 0) sms = 148;
    if (sms > 256) sms = 256;           // g_part capacity
    if (sms > TOTAL_TILES) sms = TOTAL_TILES;

    vq_main_kernel<<<sms, THREADS, SMEM_BYTES>>>(x, w, out, out_size);
}

// round 13
// speedup vs baseline: 1.1378x; 1.0021x over previous
#include <cuda_runtime.h>
#include <cstdint>

// VectorQuantizer: F=32, N=4096, D=64, K=512
// out[f,n,:] = w[f,:,k*],  k* = argmin_k ||x - w_k||^2
// loss = 1.25 * mean((quantized - inputs)^2), appended at d_out[F*N*D]
//
// R10: tiling r=4 rows/warp x kl=16 k/lane, 512 threads (16 warps, 4/SMSP).
//      Crossbar 192 cyc/d/SM < FMA 256 cyc/d/SM -> FMA-bound, and
//      acc2[4][8]=64 regs -> ~115 regs/thread, real scheduling headroom.
//      Each warp covers full k for its rows: no cross-warp combine,
//      one barrier per tile. Deterministic single-kernel loss.

#define Fh   32
#define Nh   4096
#define Dh   64
#define Kh   512
#define PADK 516                        // K + 4 floats: 16B-aligned rows
#define TILE_R 64
#define TILES_PER_F (Nh / TILE_R)       // 64
#define TOTAL_TILES (Fh * TILES_PER_F)  // 2048
#define THREADS 512

// smem: sw[64][516] f32 | swn[512] f32 | sx2[2][64*64] u64 | sxn[2][64] f32
#define SX2_OFF   (Dh * PADK + Kh)      // in floats (33536, 16B multiple)
#define SMEM_BYTES ((SX2_OFF + 2 * TILE_R * Dh * 2 + 2 * TILE_R) * 4)

__device__ double       g_part[256];
__device__ unsigned int g_count = 0;    // returns to 0 at end of every call

__device__ __forceinline__ unsigned long long ffma2(unsigned long long a,
                                                    unsigned long long b,
                                                    unsigned long long c) {
    unsigned long long d;
    asm("fma.rn.f32x2 %0, %1, %2, %3;" : "=l"(d) : "l"(a), "l"(b), "l"(c));
    return d;
}

__device__ __forceinline__ void unpack2(unsigned long long v, float& lo, float& hi) {
    unsigned int a, b;
    asm("mov.b64 {%0, %1}, %2;" : "=r"(a), "=r"(b) : "l"(v));
    lo = __uint_as_float(a);
    hi = __uint_as_float(b);
}

__global__ __launch_bounds__(THREADS, 1)
void vq_main_kernel(const float* __restrict__ x,
                    const float* __restrict__ w,
                    float* __restrict__ out,
                    int out_size) {
    extern __shared__ float smem[];
    float* sw  = smem;                                  // [Dh][PADK]
    float* swn = sw + Dh * PADK;                        // [Kh]
    unsigned long long* sx2 =
        (unsigned long long*)(smem + SX2_OFF);          // [2][TILE_R*Dh]: (-2x,-2x)
    float* sxn = (float*)(sx2 + 2 * TILE_R * Dh);       // [2][TILE_R] row ||x||^2

    __shared__ double warp_loss[16];
    __shared__ int    last_flag;

    const int tid  = threadIdx.x;
    const int wid  = tid >> 5;          // warp owns rows wid*4 .. wid*4+3
    const int lane = tid & 31;

    const int G   = gridDim.x;
    const int per = TOTAL_TILES / G;
    const int rem = TOTAL_TILES % G;
    const int t0  = blockIdx.x * per + (blockIdx.x < rem ? blockIdx.x : rem);
    const int cnt = per + (blockIdx.x < rem ? 1 : 0);
    const int tend = t0 + cnt;

    double lsum = 0.0;
    int cur_f = -1;
    int buf = 0;

    // Initial prefetch of tile t0's x (1024 float4, 2 per thread)
    float4 pf[2];
    {
        const int f0 = t0 >> 6, tl0 = t0 & 63;
        const float4* xg =
            (const float4*)(x + ((size_t)f0 * Nh + (size_t)tl0 * TILE_R) * Dh);
        #pragma unroll
        for (int j = 0; j < 2; ++j) pf[j] = xg[tid + THREADS * j];
    }

    for (int t = t0; t < tend; ++t) {
        const int f    = t >> 6;
        const int tile = t & 63;

        if (f != cur_f) {
            __syncthreads();  // prior readers of sw done
            const float4* wg = (const float4*)(w + (size_t)f * Dh * Kh);
            #pragma unroll 4
            for (int i = tid; i < Dh * (Kh / 4); i += THREADS) {
                const int d  = i >> 7;
                const int kq = i & 127;
                float4 v = wg[d * 128 + kq];
                *(float4*)&sw[d * PADK + kq * 4] = v;
            }
            __syncthreads();
            {   // one k per thread
                const int k = tid;
                float s = 0.f;
                #pragma unroll
                for (int d = 0; d < Dh; ++d) {
                    const float v = sw[d * PADK + k];
                    s = fmaf(v, v, s);
                }
                swn[k] = s;
            }
            cur_f = f;
            __syncthreads();
        }

        // ---- Store prefetched x as (-2x,-2x) pairs; row ||x||^2 ----
        {
            unsigned long long* dstb = sx2 + (size_t)buf * TILE_R * Dh;
            float s[2];
            #pragma unroll
            for (int j = 0; j < 2; ++j) {
                const int q   = tid + THREADS * j;
                const int row = q >> 4;
                const int dq  = q & 15;
                const float4 a = pf[j];
                unsigned long long* dst = dstb + row * Dh + dq * 4;
                const float nx = -2.f * a.x, ny = -2.f * a.y;
                const float nz = -2.f * a.z, nw = -2.f * a.w;
                *(float4*)(dst)     = make_float4(nx, nx, ny, ny);
                *(float4*)(dst + 2) = make_float4(nz, nz, nw, nw);
                float t2 = fmaf(a.x, a.x, a.y * a.y);
                t2 = fmaf(a.z, a.z, t2);
                s[j] = fmaf(a.w, a.w, t2);
            }
            // 16 consecutive lanes share a row
            #pragma unroll
            for (int off = 8; off > 0; off >>= 1)
                #pragma unroll
                for (int j = 0; j < 2; ++j)
                    s[j] += __shfl_xor_sync(0xffffffffu, s[j], off);
            if ((lane & 15) == 0) {
                #pragma unroll
                for (int j = 0; j < 2; ++j)
                    sxn[buf * TILE_R + ((tid + THREADS * j) >> 4)] = s[j];
            }
        }
        __syncthreads();   // single barrier per tile

        // ---- Mainloop: score_k = ||w_k||^2 + sum_d (-2 x_d) w_kd ----
        // Warp: 4 rows (wid*4..+3) x 16 k/lane (k = c*128 + lane*4 + j).
        unsigned long long acc2[4][8];
        {
            #pragma unroll
            for (int c = 0; c < 4; ++c) {
                const ulonglong2 nv =
                    *(const ulonglong2*)&swn[c * 128 + lane * 4];
                #pragma unroll
                for (int r = 0; r < 4; ++r) {
                    acc2[r][2 * c + 0] = nv.x;
                    acc2[r][2 * c + 1] = nv.y;
                }
            }
        }

        const float* swk = sw + lane * 4;
        const unsigned long long* xrow =
            sx2 + (size_t)buf * TILE_R * Dh + (wid * 4) * Dh;

        #pragma unroll 4
        for (int d = 0; d < Dh; ++d) {
            unsigned long long wp[8];
            #pragma unroll
            for (int c = 0; c < 4; ++c) {
                const ulonglong2 v =
                    *(const ulonglong2*)&swk[d * PADK + c * 128];
                wp[2 * c + 0] = v.x;
                wp[2 * c + 1] = v.y;
            }
            unsigned long long xp[4];
            #pragma unroll
            for (int r = 0; r < 4; ++r) xp[r] = xrow[r * Dh + d];  // broadcast
            #pragma unroll
            for (int r = 0; r < 4; ++r)
                #pragma unroll
                for (int j = 0; j < 8; ++j)
                    acc2[r][j] = ffma2(xp[r], wp[j], acc2[r][j]);
        }

        // ---- Per-lane argmin over 16 k (k ascending within lane) ----
        float bval[4];
        int   bidx[4];
        #pragma unroll
        for (int r = 0; r < 4; ++r) { bval[r] = 3.4e38f; bidx[r] = 0; }

        #pragma unroll
        for (int c = 0; c < 4; ++c) {
            #pragma unroll
            for (int p = 0; p < 2; ++p) {
                const int klo = c * 128 + lane * 4 + p * 2;
                #pragma unroll
                for (int r = 0; r < 4; ++r) {
                    float slo, shi;
                    unpack2(acc2[r][c * 2 + p], slo, shi);
                    if (slo < bval[r]) { bval[r] = slo; bidx[r] = klo; }
                    if (shi < bval[r]) { bval[r] = shi; bidx[r] = klo + 1; }
                }
            }
        }

        // Prefetch next tile's x (overlaps reduce latency)
        if (t + 1 < tend) {
            const int f1 = (t + 1) >> 6, tl1 = (t + 1) & 63;
            const float4* xg =
                (const float4*)(x + ((size_t)f1 * Nh + (size_t)tl1 * TILE_R) * Dh);
            #pragma unroll
            for (int j = 0; j < 2; ++j) pf[j] = xg[tid + THREADS * j];
        }

        // Warp-level argmin reduce (tie -> smaller k)
        #pragma unroll
        for (int off = 16; off > 0; off >>= 1) {
            #pragma unroll
            for (int r = 0; r < 4; ++r) {
                const float ov = __shfl_down_sync(0xffffffffu, bval[r], off);
                const int   oi = __shfl_down_sync(0xffffffffu, bidx[r], off);
                if (ov < bval[r] || (ov == bval[r] && oi < bidx[r])) {
                    bval[r] = ov; bidx[r] = oi;
                }
            }
        }
        // Loss: dist = ||x||^2 + min score
        if (lane == 0) {
            #pragma unroll
            for (int r = 0; r < 4; ++r)
                lsum += (double)(bval[r] + sxn[buf * TILE_R + wid * 4 + r]);
        }
        #pragma unroll
        for (int r = 0; r < 4; ++r)
            bidx[r] = __shfl_sync(0xffffffffu, bidx[r], 0);

        // ---- Gather winning codewords, write output ----
        #pragma unroll
        for (int r = 0; r < 4; ++r) {
            const int kst = bidx[r];
            const int n = tile * TILE_R + wid * 4 + r;
            float* orow = out + ((size_t)f * Nh + n) * Dh;
            #pragma unroll
            for (int it = 0; it < 2; ++it) {
                const int d = it * 32 + lane;
                orow[d] = sw[d * PADK + kst];
            }
        }
        buf ^= 1;
    }

    // ---- Block partial -> last-block deterministic reduction ----
    if (lane == 0) warp_loss[wid] = lsum;
    __syncthreads();
    if (tid == 0) {
        double bl = 0.0;
        #pragma unroll
        for (int i = 0; i < 16; ++i) bl += warp_loss[i];
        g_part[blockIdx.x] = bl;
        __threadfence();
        const unsigned c = atomicAdd(&g_count, 1u);
        last_flag = (c == (unsigned)(G - 1)) ? 1 : 0;
    }
    __syncthreads();
    if (last_flag && wid == 0) {
        double s = 0.0;
        for (int i = lane; i < G; i += 32) s += g_part[i];
        #pragma unroll
        for (int off = 16; off > 0; off >>= 1)
            s += __shfl_down_sync(0xffffffffu, s, off);
        if (lane == 0) {
            const long long nelem = (long long)Fh * Nh * Dh;
            if (out_size > (int)nelem)
                out[nelem] = (float)(1.25 * s / (double)nelem);
            g_count = 0;   // reset for next call
        }
    }
}

extern "C" void kernel_launch(void* const* d_in, const int* in_sizes, int n_in,
                              void* d_out, int out_size) {
    const float* x = (const float*)d_in[0];
    const float* w = (const float*)d_in[1];
    if (n_in >= 2 && in_sizes[0] == Fh * Dh * Kh && in_sizes[1] == Fh * Nh * Dh) {
        const float* tmp = x; x = w; w = tmp;
    }
    float* out = (float*)d_out;

    cudaFuncSetAttribute(vq_main_kernel,
                         cudaFuncAttributeMaxDynamicSharedMemorySize, SMEM_BYTES);

    int sms = 148;
    cudaDeviceGetAttribute(&sms, cudaDevAttrMultiProcessorCount, 0);
    if (sms <= 0) sms = 148;
    if (sms > 256) sms = 256;           // g_part capacity
    if (sms > TOTAL_TILES) sms = TOTAL_TILES;

    vq_main_kernel<<<sms, THREADS, SMEM_BYTES>>>(x, w, out, out_size);
}

// round 17
// speedup vs baseline: 1.1815x; 1.0384x over previous
#include <cuda_runtime.h>
#include <cuda_bf16.h>
#include <cstdint>

// VectorQuantizer: F=32, N=4096, D=64, K=512 — mma.sync bf16 3-split GEMM.
// out[f,n,:] = w[f,:,k*], k* = argmin_k ||x-w_k||^2; loss at out[F*N*D].
//
// R15: tcgen05 blocked (PTX targets sm_103 w/o 'a'); use HMMA via
// mma.sync.m16n8k16.bf16.f32 + ldmatrix. score = ||w||^2 + (-2x)·w with
// 3-way bf16 splits, 8 passes (drop only a2b2 ~2^-32) -> fp32-grade scores.

#define Fh 32
#define Nh 4096
#define Dh 64
#define Kh 512
#define TILE_R 128
#define TILES_PER_F 32
#define TOTAL_TILES 1024
#define THREADS 256

// smem byte offsets. Row stride 144B (72 bf16) keeps ldmatrix conflict-free.
#define ASTRIDE 144
#define A_OFF   0                    // 3 x [128 x 144B] = 55296
#define A_SPL   18432
#define B_OFF   55296                // 3 x [256 x 144B] = 110592
#define B_SPL   36864
#define SWN_OFF 165888               // f32[256]
#define SXN_OFF 166912               // f32[128]
#define STV_OFF 167424               // f32[8*128]
#define STI_OFF 171520               // i32[8*128]
#define SMEM_BYTES 175616

__device__ double       g_part[256];
__device__ unsigned int g_count = 0;

__device__ __forceinline__ uint32_t s2u(const void* p) {
    uint32_t a;
    asm("{ .reg .u64 t; cvta.to.shared.u64 t, %1; cvt.u32.u64 %0, t; }" : "=r"(a) : "l"(p));
    return a;
}
__device__ __forceinline__ void ldsm4(uint32_t* r, uint32_t addr) {
    asm volatile("ldmatrix.sync.aligned.m8n8.x4.shared.b16 {%0,%1,%2,%3}, [%4];"
                 : "=r"(r[0]), "=r"(r[1]), "=r"(r[2]), "=r"(r[3]) : "r"(addr));
}
__device__ __forceinline__ void ldsm2(uint32_t* r, uint32_t addr) {
    asm volatile("ldmatrix.sync.aligned.m8n8.x2.shared.b16 {%0,%1}, [%2];"
                 : "=r"(r[0]), "=r"(r[1]) : "r"(addr));
}
__device__ __forceinline__ void mma16816(float* c, const uint32_t* a, const uint32_t* b) {
    asm volatile("mma.sync.aligned.m16n8k16.row.col.f32.bf16.bf16.f32 "
                 "{%0,%1,%2,%3}, {%4,%5,%6,%7}, {%8,%9}, {%0,%1,%2,%3};"
                 : "+f"(c[0]), "+f"(c[1]), "+f"(c[2]), "+f"(c[3])
                 : "r"(a[0]), "r"(a[1]), "r"(a[2]), "r"(a[3]), "r"(b[0]), "r"(b[1]));
}
__device__ __forceinline__ void split3(float a, __nv_bfloat16& b0,
                                       __nv_bfloat16& b1, __nv_bfloat16& b2) {
    b0 = __float2bfloat16(a); float r = a - __bfloat162float(b0);
    b1 = __float2bfloat16(r); r = r - __bfloat162float(b1);
    b2 = __float2bfloat16(r);
}
__device__ __forceinline__ uint32_t pk(__nv_bfloat16 a, __nv_bfloat16 b) {
    uint16_t ua = *(uint16_t*)&a, ub = *(uint16_t*)&b;
    return (uint32_t)ua | ((uint32_t)ub << 16);
}
__device__ __forceinline__ float2 bf2f(uint32_t u) {
    __nv_bfloat162 h = *reinterpret_cast<__nv_bfloat162*>(&u);
    return __bfloat1622float2(h);
}

__global__ __launch_bounds__(THREADS, 1)
void vq_mma_kernel(const float* __restrict__ x, const float* __restrict__ w,
                   float* __restrict__ out, int out_size) {
    extern __shared__ char sm[];
    const uint32_t sb = s2u(sm);
    float* swn = (float*)(sm + SWN_OFF);
    float* sxn = (float*)(sm + SXN_OFF);
    float* stv = (float*)(sm + STV_OFF);
    int*   sti = (int*)(sm + STI_OFF);
    __shared__ double wls[8];
    __shared__ int lflag;

    const int tid = threadIdx.x, wid = tid >> 5, lane = tid & 31;
    const int m0 = wid * 16;                 // this warp's row tile

    const int G = gridDim.x;
    const int per = TOTAL_TILES / G, rem = TOTAL_TILES % G;
    const int t0 = blockIdx.x * per + (blockIdx.x < rem ? blockIdx.x : rem);
    const int tend = t0 + per + (blockIdx.x < rem ? 1 : 0);

    double lsum = 0.0;

    int t = t0;
    while (t < tend) {
        const int f = t >> 5;
        const int segEnd = min(tend, (f + 1) << 5);
        const int segN = segEnd - t;
        const float* wf = w + (size_t)f * Dh * Kh;

        for (int half = 0; half < 2; ++half) {
            // ---- B splits + ||w||^2 for this 256-k half (k = tid) ----
            {
                float s = 0.f;
                const float* p = wf + half * 256 + tid;
                char* b0p = sm + B_OFF + tid * ASTRIDE;
                #pragma unroll 8
                for (int d = 0; d < Dh; ++d) {
                    const float v = p[(size_t)d * Kh];
                    s = fmaf(v, v, s);
                    __nv_bfloat16 c0, c1, c2;
                    split3(v, c0, c1, c2);
                    *(__nv_bfloat16*)(b0p + d * 2)             = c0;
                    *(__nv_bfloat16*)(b0p + B_SPL + d * 2)     = c1;
                    *(__nv_bfloat16*)(b0p + 2 * B_SPL + d * 2) = c2;
                }
                swn[tid] = s;
            }

            for (int s = 0; s < segN; ++s) {
                const int tt = t + s, tile = tt & 31;

                // ---- A splits = -2x (thread pair per row), row ||x||^2 ----
                {
                    const int r = tid >> 1, hrow = tid & 1, d0 = hrow * 32;
                    const float4* xr = (const float4*)(x +
                        ((size_t)f * Nh + (size_t)tile * TILE_R + r) * Dh + d0);
                    char* ap = sm + A_OFF + r * ASTRIDE + d0 * 2;
                    float xn = 0.f;
                    #pragma unroll
                    for (int q = 0; q < 8; ++q) {
                        const float4 v = xr[q];
                        xn = fmaf(v.x, v.x, fmaf(v.y, v.y,
                             fmaf(v.z, v.z, fmaf(v.w, v.w, xn))));
                        __nv_bfloat16 c0[4], c1[4], c2[4];
                        split3(-2.f * v.x, c0[0], c1[0], c2[0]);
                        split3(-2.f * v.y, c0[1], c1[1], c2[1]);
                        split3(-2.f * v.z, c0[2], c1[2], c2[2]);
                        split3(-2.f * v.w, c0[3], c1[3], c2[3]);
                        *(uint2*)(ap + q * 8) =
                            make_uint2(pk(c0[0], c0[1]), pk(c0[2], c0[3]));
                        *(uint2*)(ap + A_SPL + q * 8) =
                            make_uint2(pk(c1[0], c1[1]), pk(c1[2], c1[3]));
                        *(uint2*)(ap + 2 * A_SPL + q * 8) =
                            make_uint2(pk(c2[0], c2[1]), pk(c2[2], c2[3]));
                    }
                    xn += __shfl_xor_sync(0xffffffffu, xn, 1);
                    if (hrow == 0) sxn[r] = xn;
                }
                __syncthreads();

                // ---- MMA: 4 chunks of 8 n-tiles; 8 split passes ----
                float bv0 = 3.4e38f, bv1 = 3.4e38f;
                int   bi0 = 0, bi1 = 0;
                const int arow = lane & 15, akb = lane >> 4;
                const int brow = lane & 7,  bkb = (lane >> 3) & 1;
                const uint32_t aBase = sb + A_OFF + (m0 + arow) * ASTRIDE + akb * 16;
                const uint32_t bBase = sb + B_OFF + brow * ASTRIDE + bkb * 16;

                static const int PA[8] = {0, 0, 1, 1, 2, 0, 1, 2};
                static const int PB[8] = {0, 1, 0, 1, 0, 2, 2, 1};

                #pragma unroll
                for (int ch = 0; ch < 4; ++ch) {
                    float acc[8][4];
                    #pragma unroll
                    for (int nt = 0; nt < 8; ++nt)
                        acc[nt][0] = acc[nt][1] = acc[nt][2] = acc[nt][3] = 0.f;

                    #pragma unroll
                    for (int ks = 0; ks < 4; ++ks) {
                        uint32_t A[3][4], B[8][3][2];
                        #pragma unroll
                        for (int sp = 0; sp < 3; ++sp)
                            ldsm4(A[sp], aBase + sp * A_SPL + ks * 32);
                        #pragma unroll
                        for (int nt = 0; nt < 8; ++nt)
                            #pragma unroll
                            for (int sp = 0; sp < 3; ++sp)
                                ldsm2(B[nt][sp], bBase + (ch * 64 + nt * 8) * ASTRIDE
                                                 + sp * B_SPL + ks * 32);
                        #pragma unroll
                        for (int p = 0; p < 8; ++p)
                            #pragma unroll
                            for (int nt = 0; nt < 8; ++nt)
                                mma16816(acc[nt], A[PA[p]], B[nt][PB[p]]);
                    }

                    // epilogue: + ||w||^2, streaming argmin (k ascending)
                    #pragma unroll
                    for (int nt = 0; nt < 8; ++nt) {
                        const int cloc = ch * 64 + nt * 8 + (lane & 3) * 2;
                        const float wn0 = swn[cloc], wn1 = swn[cloc + 1];
                        const int kg = half * 256 + cloc;
                        const float s0 = acc[nt][0] + wn0;
                        const float s1 = acc[nt][1] + wn1;
                        const float s2 = acc[nt][2] + wn0;
                        const float s3 = acc[nt][3] + wn1;
                        if (s0 < bv0) { bv0 = s0; bi0 = kg; }
                        if (s1 < bv0) { bv0 = s1; bi0 = kg + 1; }
                        if (s2 < bv1) { bv1 = s2; bi1 = kg; }
                        if (s3 < bv1) { bv1 = s3; bi1 = kg + 1; }
                    }
                }

                // cross-lane combine among the 4 threads sharing each row
                #pragma unroll
                for (int off = 1; off <= 2; off <<= 1) {
                    const float o0 = __shfl_xor_sync(0xffffffffu, bv0, off);
                    const int   i0 = __shfl_xor_sync(0xffffffffu, bi0, off);
                    const float o1 = __shfl_xor_sync(0xffffffffu, bv1, off);
                    const int   i1 = __shfl_xor_sync(0xffffffffu, bi1, off);
                    if (o0 < bv0 || (o0 == bv0 && i0 < bi0)) { bv0 = o0; bi0 = i0; }
                    if (o1 < bv1 || (o1 == bv1 && i1 < bi1)) { bv1 = o1; bi1 = i1; }
                }

                const int g = lane >> 2;
                if ((lane & 3) == 0) {
                    const int i0s = s * 128 + m0 + g;
                    const int i1s = i0s + 8;
                    if (half == 0) {
                        stv[i0s] = bv0; sti[i0s] = bi0;
                        stv[i1s] = bv1; sti[i1s] = bi1;
                    } else {
                        const float p0 = stv[i0s], p1 = stv[i1s];
                        const int   q0 = sti[i0s], q1 = sti[i1s];
                        if (!(bv0 < p0)) { bv0 = p0; bi0 = q0; }
                        if (!(bv1 < p1)) { bv1 = p1; bi1 = q1; }
                        sti[i0s] = bi0; sti[i1s] = bi1;
                        lsum += (double)(bv0 + sxn[m0 + g]);
                        lsum += (double)(bv1 + sxn[m0 + g + 8]);
                    }
                }
                __syncwarp();

                // ---- gather codewords (b0+b1+b2) for this warp's 16 rows ----
                #pragma unroll
                for (int r = 0; r < 16; ++r) {
                    const int ki = sti[s * 128 + m0 + r];
                    if (half == 1 && ki < 256) continue;   // winner stays from half0
                    const int kk = ki & 255;
                    const char* bp = sm + B_OFF + kk * ASTRIDE + lane * 4;
                    const float2 f0 = bf2f(*(const uint32_t*)bp);
                    const float2 f1 = bf2f(*(const uint32_t*)(bp + B_SPL));
                    const float2 f2 = bf2f(*(const uint32_t*)(bp + 2 * B_SPL));
                    float2 o;
                    o.x = f0.x + f1.x + f2.x;
                    o.y = f0.y + f1.y + f2.y;
                    *(float2*)(out + ((size_t)f * Nh + (size_t)tile * TILE_R
                               + m0 + r) * Dh + lane * 2) = o;
                }
                __syncthreads();   // protect A (and B at half swap) before refill
            }
        }
        t = segEnd;
    }

    // ---- deterministic loss reduction ----
    #pragma unroll
    for (int off = 16; off > 0; off >>= 1)
        lsum += __shfl_down_sync(0xffffffffu, lsum, off);
    if (lane == 0) wls[wid] = lsum;
    __syncthreads();
    if (tid == 0) {
        double bl = 0.0;
        #pragma unroll
        for (int i = 0; i < 8; ++i) bl += wls[i];
        g_part[blockIdx.x] = bl;
        __threadfence();
        const unsigned c = atomicAdd(&g_count, 1u);
        lflag = (c == (unsigned)(G - 1)) ? 1 : 0;
    }
    __syncthreads();
    if (lflag && wid == 0) {
        double s = 0.0;
        for (int i = lane; i < G; i += 32) s += g_part[i];
        #pragma unroll
        for (int off = 16; off > 0; off >>= 1)
            s += __shfl_down_sync(0xffffffffu, s, off);
        if (lane == 0) {
            const long long nelem = (long long)Fh * Nh * Dh;
            if (out_size > (int)nelem)
                out[nelem] = (float)(1.25 * s / (double)nelem);
            g_count = 0;
        }
    }
}

extern "C" void kernel_launch(void* const* d_in, const int* in_sizes, int n_in,
                              void* d_out, int out_size) {
    const float* x = (const float*)d_in[0];
    const float* w = (const float*)d_in[1];
    if (n_in >= 2 && in_sizes[0] == Fh * Dh * Kh && in_sizes[1] == Fh * Nh * Dh) {
        const float* tmp = x; x = w; w = tmp;
    }
    float* out = (float*)d_out;

    cudaFuncSetAttribute(vq_mma_kernel,
                         cudaFuncAttributeMaxDynamicSharedMemorySize, SMEM_BYTES);

    int sms = 148;
    cudaDeviceGetAttribute(&sms, cudaDevAttrMultiProcessorCount, 0);
    if (sms <= 0) sms = 148;
    int G = sms;
    if (G < 128) G = 128;               // keeps per-CTA tiles <= 8 (state slots)
    if (G > 256) G = 256;               // g_part capacity

    vq_mma_kernel<<<G, THREADS, SMEM_BYTES>>>(x, w, out, out_size);
}